// round 15
// baseline (speedup 1.0000x reference)
#include <cuda_runtime.h>
#include <cstdint>

#define TT 65536
#define KK 512
#define NEGV (-10000.0f)
#define CSZ 16            // cluster CTAs
#define NPC 32            // next-rows per CTA
#define NTHR 256          // 8 warps
#define LBT 256
#define BBT (TT/LBT)
#define CH_TX 256u        // 32 msgs x 8B per chunk barrier per step
#define GG 64             // bp-pass t-partitions (1024 CTAs)
#define SPAN (TT/GG)

// ---- static device scratch ----
__device__ float          g_fv[(size_t)TT * KK];   // fv history
__device__ unsigned short g_bp[(size_t)TT * KK];   // backpointers
__device__ unsigned short g_maps[BBT * KK];
__device__ int            g_endtag[BBT];
__device__ int            g_best;

__device__ __forceinline__ uint32_t smem_u32(const void* p) {
    return (uint32_t)__cvta_generic_to_shared(p);
}
__device__ __forceinline__ uint32_t mapa_u32(uint32_t laddr, int r) {
    uint32_t ra;
    asm("mapa.shared::cluster.u32 %0, %1, %2;" : "=r"(ra) : "r"(laddr), "r"(r));
    return ra;
}
__device__ __forceinline__ void st_async_b64(uint32_t raddr, unsigned long long v,
                                             uint32_t rmbar) {
    asm volatile(
        "st.async.weak.shared::cluster.mbarrier::complete_tx::bytes.b64 [%0], %1, [%2];"
        :: "r"(raddr), "l"(v), "r"(rmbar) : "memory");
}
__device__ __forceinline__ void mbar_init(uint32_t a, uint32_t cnt) {
    asm volatile("mbarrier.init.shared.b64 [%0], %1;" :: "r"(a), "r"(cnt) : "memory");
}
__device__ __forceinline__ void mbar_expect_tx(uint32_t a, uint32_t bytes) {
    asm volatile("mbarrier.arrive.expect_tx.shared.b64 _, [%0], %1;"
                 :: "r"(a), "r"(bytes) : "memory");
}
__device__ __forceinline__ void mbar_complete_tx(uint32_t a, uint32_t bytes) {
    asm volatile("mbarrier.complete_tx.shared.b64 [%0], %1;"
                 :: "r"(a), "r"(bytes) : "memory");
}
__device__ __forceinline__ void mbar_wait(uint32_t a, uint32_t parity) {
    uint32_t done;
    asm volatile(
        "{\n\t.reg .pred p;\n\t"
        "mbarrier.try_wait.parity.acquire.cta.shared::cta.b64 p, [%1], %2;\n\t"
        "selp.b32 %0, 1, 0, p;\n\t}"
        : "=r"(done) : "r"(a), "r"(parity) : "memory");
    if (!done) {
        asm volatile(
            "{\n\t.reg .pred P1;\n\t"
            "W_%=:\n\t"
            "mbarrier.try_wait.parity.acquire.cta.shared::cta.b64 P1, [%0], %1, 0x989680;\n\t"
            "@P1 bra.uni D_%=;\n\t"
            "bra.uni W_%=;\n\t"
            "D_%=:\n\t}"
            :: "r"(a), "r"(parity) : "memory");
    }
}
__device__ __forceinline__ void cluster_sync_() {
    asm volatile("barrier.cluster.arrive.aligned;" ::: "memory");
    asm volatile("barrier.cluster.wait.aligned;" ::: "memory");
}
__device__ __forceinline__ uint32_t ctarank() {
    uint32_t r; asm("mov.u32 %0, %%cluster_ctarank;" : "=r"(r)); return r;
}

// ---- kernel 1: per-chunk-barrier dataflow; shfl moved off critical path ----
__global__ void __launch_bounds__(NTHR, 1)
viterbi_fwd(const float* __restrict__ feats, const float* __restrict__ trans,
            float* __restrict__ dout, int idx0)
{
    __shared__ __align__(16) float fvbuf[2][KK];        // buf1 at +2048B
    __shared__ __align__(8) float pval[2][8][NPC];      // parity-double-buffered
    __shared__ __align__(8) unsigned long long cmbar[2][8];  // [parity][chunk]
    __shared__ float tv[NTHR];
    __shared__ int   ti[NTHR];

    const int tid  = threadIdx.x;
    const int lane = tid & 31;      // next-row within CTA
    const int w    = tid >> 5;      // warp w == prev chunk w
    const uint32_t rank = ctarank();
    const int n = (int)rank * NPC + lane;

    // transitions slice trans[n, w*64 .. +64) -> registers (broadcast-read layout)
    float Tr[64];
    {
        const float4* tp = (const float4*)(trans + (size_t)n * KK + w * 64);
        #pragma unroll
        for (int q = 0; q < 16; q++) {
            float4 v = tp[q];
            Tr[4*q] = v.x; Tr[4*q+1] = v.y; Tr[4*q+2] = v.z; Tr[4*q+3] = v.w;
        }
    }

    const uint32_t mbb = smem_u32(&cmbar[0][0]);   // [par][c] at mbb + par*64 + c*8

    // init fv_{-1} in buf[1]; init barriers; pre-complete [1][c] phase 0
    for (int p = tid; p < KK; p += NTHR) fvbuf[1][p] = (p == 0) ? 0.0f : NEGV;
    if (tid < 8) {
        mbar_init(mbb + (uint32_t)tid * 8u, 1);          // [0][tid]
        mbar_init(mbb + 64u + (uint32_t)tid * 8u, 1);    // [1][tid]
        mbar_expect_tx(mbb + 64u + (uint32_t)tid * 8u, CH_TX);
        mbar_complete_tx(mbb + 64u + (uint32_t)tid * 8u, CH_TX);
    }
    __syncthreads();
    cluster_sync_();

    // push: warp w -> dest CTAs 2w, 2w+1; even lanes carry rows (n, n+1);
    // dest chunk barrier index = rank>>1
    uint32_t rd0, rd1, rm0, rm1;
    {
        const uint32_t a0 = smem_u32(&fvbuf[0][n]);       // n even for pushing lanes
        const uint32_t mB = mbb + (rank >> 1) * 8u;       // [0][rank>>1]
        rd0 = mapa_u32(a0, 2 * w);
        rd1 = mapa_u32(a0, 2 * w + 1);
        rm0 = mapa_u32(mB, 2 * w);
        rm1 = mapa_u32(mB, 2 * w + 1);
    }
    const uint32_t myb = mbb + (uint32_t)w * 8u;          // my chunk barriers

    // feats prefetch (all lanes, coalesced scalar); odd-row copy via prefetch-path shfl
    float ft0  = __ldg(feats + n);
    float ft0h = __shfl_down_sync(0xffffffffu, ft0, 1);
    float ft1  = __ldg(feats + KK + n);
    float ft1h = __shfl_down_sync(0xffffffffu, ft1, 1);

    #define STEP(T, PAR) do {                                                      \
        if (lane == 0) mbar_expect_tx(myb + (PAR)*64u, CH_TX);                     \
        float ftn;                                                                 \
        {                                                                          \
            int tn = (T) + 2; if (tn > TT - 1) tn = TT - 1;                        \
            ftn = __ldg(feats + (size_t)tn * KK + n);                              \
        }                                                                          \
        const float ftnh = __shfl_down_sync(0xffffffffu, ftn, 1);                  \
        mbar_wait(myb + ((PAR)^1)*64u, ((T) >> 1) & 1);   /* my chunk ready */     \
        const float4* fvp = (const float4*)&fvbuf[(PAR) ^ 1][w * 64];              \
        float m0 = -INFINITY, m1 = -INFINITY, m2 = -INFINITY, m3 = -INFINITY;      \
        _Pragma("unroll")                                                          \
        for (int q = 0; q < 16; q++) {                                             \
            float4 f = fvp[q];            /* 32-lane broadcast, conflict-free */   \
            m0 = fmaxf(m0, f.x + Tr[4*q]);                                         \
            m1 = fmaxf(m1, f.y + Tr[4*q+1]);                                       \
            m2 = fmaxf(m2, f.z + Tr[4*q+2]);                                       \
            m3 = fmaxf(m3, f.w + Tr[4*q+3]);                                       \
        }                                                                          \
        pval[PAR][w][lane] = fmaxf(fmaxf(m0, m1), fmaxf(m2, m3));                  \
        __syncthreads();                                /* single sync per step */ \
        if ((lane & 1) == 0) {         /* even lanes: rows n, n+1; no shfl */      \
            float vx = pval[PAR][0][lane];                                         \
            float vy = pval[PAR][0][lane + 1];                                     \
            _Pragma("unroll")                                                      \
            for (int c = 1; c < 8; c++) {                                          \
                vx = fmaxf(vx, pval[PAR][c][lane]);                                \
                vy = fmaxf(vy, pval[PAR][c][lane + 1]);                            \
            }                                                                      \
            const float fv0 = vx + ft0;           /* exact: max + emission */      \
            const float fv1 = vy + ft0h;                                           \
            if (w == 0)                                                            \
                *(float2*)&g_fv[(size_t)(T) * KK + n] = make_float2(fv0, fv1);     \
            unsigned long long pk =                                                \
                ((unsigned long long)__float_as_uint(fv1) << 32) |                 \
                (unsigned long long)__float_as_uint(fv0);                          \
            st_async_b64(rd0 + (PAR)*2048u, pk, rm0 + (PAR)*64u);                  \
            st_async_b64(rd1 + (PAR)*2048u, pk, rm1 + (PAR)*64u);                  \
        }                                                                          \
        ft0 = ft1; ft0h = ft1h; ft1 = ftn; ft1h = ftnh;                            \
    } while (0)

    for (int t = 0; t < TT; t += 2) {
        STEP(t, 0);
        STEP(t + 1, 1);
    }
    #undef STEP

    // drain final-step messages (buf[1], barrier [1][w])
    mbar_wait(myb + 64u, (TT >> 1) & 1);
    __syncthreads();

    // terminal = fv_{TT-1} + trans[1,:]; first-index argmax (rank 0)
    if (rank == 0) {
        float v = -INFINITY; int i = 0;
        #pragma unroll
        for (int k = 0; k < KK / NTHR; k++) {
            const int p = tid * (KK / NTHR) + k;
            const float s = fvbuf[1][p] + trans[KK + p];
            if (s > v) { v = s; i = p; }
        }
        tv[tid] = v; ti[tid] = i;
        __syncthreads();
        if (tid == 0) {
            float bv = tv[0]; int bi = ti[0];
            for (int k = 1; k < NTHR; k++)
                if (tv[k] > bv || (tv[k] == bv && ti[k] < bi)) { bv = tv[k]; bi = ti[k]; }
            if (idx0 > 0) dout[0] = bv;
            g_best = bi;
        }
    }
    cluster_sync_();   // keep cluster alive until all remote traffic done
}

// ---- kernel 2: parallel backpointer recompute (exact argmax) ----
__global__ void __launch_bounds__(NTHR, 1)
bp_pass(const float* __restrict__ trans)
{
    __shared__ __align__(16) float fvs[2][KK];   // transposed staging

    const int rblk = blockIdx.x & 15;
    const int g    = blockIdx.x >> 4;
    const int t0   = g * SPAN;
    const int t1   = t0 + SPAN;

    const int tid   = threadIdx.x;
    const int lane  = tid & 31;
    const int w     = tid >> 5;
    const int rl    = lane & 3;
    const int chunk = lane >> 2;
    const int n = rblk * NPC + w * 4 + rl;

    float Tr[64];
    {
        const float4* tp = (const float4*)(trans + (size_t)n * KK + chunk * 64);
        #pragma unroll
        for (int q = 0; q < 16; q++) {
            float4 v = tp[q];
            Tr[4*q] = v.x; Tr[4*q+1] = v.y; Tr[4*q+2] = v.z; Tr[4*q+3] = v.w;
        }
    }

    const int sp = 2 * tid;
    const uint32_t sbyte = (uint32_t)(((sp & 63) >> 2) * 128 + (sp >> 6) * 16 + (sp & 3) * 4);

    float2 pre;
    if (t0 == 0) {
        pre.x = (sp == 0) ? 0.0f : NEGV;
        pre.y = NEGV;
    } else {
        pre = *(const float2*)&g_fv[(size_t)(t0 - 1) * KK + sp];
    }

    int cur = 0;
    for (int t = t0; t < t1; ++t) {
        *(float2*)((char*)&fvs[cur][0] + sbyte) = pre;
        __syncthreads();
        if (t + 1 < t1) pre = *(const float2*)&g_fv[(size_t)t * KK + sp];

        const char* sm = (const char*)&fvs[cur][0] + chunk * 16;
        float bv0 = -INFINITY, bv1 = -INFINITY, bv2 = -INFINITY, bv3 = -INFINITY;
        int   bj0 = 0, bj1 = 0, bj2 = 0, bj3 = 0;
        #pragma unroll
        for (int q = 0; q < 16; q++) {
            float4 f = *(const float4*)(sm + q * 128);
            float s0 = f.x + Tr[4*q],   s1 = f.y + Tr[4*q+1];
            float s2 = f.z + Tr[4*q+2], s3 = f.w + Tr[4*q+3];
            bool g0 = s0 > bv0; bv0 = g0 ? s0 : bv0; bj0 = g0 ? 4*q : bj0;
            bool g1 = s1 > bv1; bv1 = g1 ? s1 : bv1; bj1 = g1 ? 4*q : bj1;
            bool g2 = s2 > bv2; bv2 = g2 ? s2 : bv2; bj2 = g2 ? 4*q : bj2;
            bool g3 = s3 > bv3; bv3 = g3 ? s3 : bv3; bj3 = g3 ? 4*q : bj3;
        }
        int i0 = chunk*64 + bj0, i1 = chunk*64 + bj1 + 1;
        int i2 = chunk*64 + bj2 + 2, i3 = chunk*64 + bj3 + 3;
        if (bv1 > bv0 || (bv1 == bv0 && i1 < i0)) { bv0 = bv1; i0 = i1; }
        if (bv3 > bv2 || (bv3 == bv2 && i3 < i2)) { bv2 = bv3; i2 = i3; }
        if (bv2 > bv0 || (bv2 == bv0 && i2 < i0)) { bv0 = bv2; i0 = i2; }

        float v = bv0; int i = i0;
        #pragma unroll
        for (int d = 4; d <= 16; d <<= 1) {
            float vo = __shfl_xor_sync(0xffffffffu, v, d);
            int   io = __shfl_xor_sync(0xffffffffu, i, d);
            if (vo > v || (vo == v && io < i)) { v = vo; i = io; }
        }
        if (chunk == 0)
            g_bp[(size_t)t * KK + n] = (unsigned short)i;
        cur ^= 1;
    }
}

// ---- kernel 3: per-block backtrack maps ----
__global__ void bt_maps()
{
    __shared__ unsigned short rbuf[KK];
    const int b = blockIdx.x, tid = threadIdx.x;
    int x = tid;
    for (int s = LBT - 1; s >= 0; --s) {
        const size_t t = (size_t)b * LBT + s;
        rbuf[tid] = g_bp[t * KK + tid];
        __syncthreads();
        x = rbuf[x];
        __syncthreads();
    }
    g_maps[b * KK + tid] = (unsigned short)x;
}

// ---- kernel 4: compose block maps ----
__global__ void bt_compose()
{
    int e = g_best;
    g_endtag[BBT - 1] = e;
    for (int b = BBT - 1; b >= 1; --b) {
        e = g_maps[b * KK + e];
        g_endtag[b - 1] = e;
    }
}

// ---- kernel 5: fill best_path ----
__global__ void bt_fill(float* __restrict__ dout, int idx0)
{
    const int b = blockIdx.x;
    int x = g_endtag[b];
    for (int s = LBT - 1; s >= 0; --s) {
        const size_t t = (size_t)b * LBT + s;
        dout[idx0 + t] = (float)x;
        x = g_bp[t * KK + x];
    }
}

extern "C" void kernel_launch(void* const* d_in, const int* in_sizes, int n_in,
                              void* d_out, int out_size)
{
    const float* feats = (const float*)d_in[0];
    const float* trans = (const float*)d_in[1];
    float* out = (float*)d_out;
    int idx0 = out_size - TT; if (idx0 < 0) idx0 = 0;

    cudaFuncSetAttribute(viterbi_fwd,
                         cudaFuncAttributeNonPortableClusterSizeAllowed, 1);
    cudaLaunchConfig_t cfg = {};
    cfg.gridDim  = dim3(CSZ, 1, 1);
    cfg.blockDim = dim3(NTHR, 1, 1);
    cfg.dynamicSmemBytes = 0;
    cfg.stream = 0;
    cudaLaunchAttribute at[1];
    at[0].id = cudaLaunchAttributeClusterDimension;
    at[0].val.clusterDim.x = CSZ;
    at[0].val.clusterDim.y = 1;
    at[0].val.clusterDim.z = 1;
    cfg.attrs = at; cfg.numAttrs = 1;
    cudaLaunchKernelEx(&cfg, viterbi_fwd, feats, trans, out, idx0);

    bp_pass<<<16 * GG, NTHR>>>(trans);
    bt_maps<<<BBT, KK>>>();
    bt_compose<<<1, 1>>>();
    bt_fill<<<BBT, 1>>>(out, idx0);
}

// round 16
// speedup vs baseline: 1.1696x; 1.1696x over previous
#include <cuda_runtime.h>
#include <cstdint>

#define TT 65536
#define KK 512
#define NEGV (-10000.0f)
#define CSZ 16            // cluster CTAs
#define NPC 32            // next-rows per CTA
#define FWT 512           // forward threads: 16 warps
#define NTHR 256          // bp_pass threads
#define LBT 256
#define BBT (TT/LBT)
#define CH_TX 256u        // 2 source CTAs x 16 msgs x 8B per chunk barrier
#define GG 64             // bp-pass t-partitions (1024 CTAs)
#define SPAN (TT/GG)

// ---- static device scratch ----
__device__ float          g_fv[(size_t)TT * KK];   // fv history
__device__ unsigned short g_bp[(size_t)TT * KK];   // backpointers
__device__ unsigned short g_maps[BBT * KK];
__device__ int            g_endtag[BBT];
__device__ int            g_best;

__device__ __forceinline__ uint32_t smem_u32(const void* p) {
    return (uint32_t)__cvta_generic_to_shared(p);
}
__device__ __forceinline__ uint32_t mapa_u32(uint32_t laddr, int r) {
    uint32_t ra;
    asm("mapa.shared::cluster.u32 %0, %1, %2;" : "=r"(ra) : "r"(laddr), "r"(r));
    return ra;
}
__device__ __forceinline__ void st_async_b64(uint32_t raddr, unsigned long long v,
                                             uint32_t rmbar) {
    asm volatile(
        "st.async.weak.shared::cluster.mbarrier::complete_tx::bytes.b64 [%0], %1, [%2];"
        :: "r"(raddr), "l"(v), "r"(rmbar) : "memory");
}
__device__ __forceinline__ void mbar_init(uint32_t a, uint32_t cnt) {
    asm volatile("mbarrier.init.shared.b64 [%0], %1;" :: "r"(a), "r"(cnt) : "memory");
}
__device__ __forceinline__ void mbar_expect_tx(uint32_t a, uint32_t bytes) {
    asm volatile("mbarrier.arrive.expect_tx.shared.b64 _, [%0], %1;"
                 :: "r"(a), "r"(bytes) : "memory");
}
__device__ __forceinline__ void mbar_complete_tx(uint32_t a, uint32_t bytes) {
    asm volatile("mbarrier.complete_tx.shared.b64 [%0], %1;"
                 :: "r"(a), "r"(bytes) : "memory");
}
__device__ __forceinline__ void mbar_wait(uint32_t a, uint32_t parity) {
    uint32_t done;
    asm volatile(
        "{\n\t.reg .pred p;\n\t"
        "mbarrier.try_wait.parity.acquire.cta.shared::cta.b64 p, [%1], %2;\n\t"
        "selp.b32 %0, 1, 0, p;\n\t}"
        : "=r"(done) : "r"(a), "r"(parity) : "memory");
    if (!done) {
        asm volatile(
            "{\n\t.reg .pred P1;\n\t"
            "W_%=:\n\t"
            "mbarrier.try_wait.parity.acquire.cta.shared::cta.b64 P1, [%0], %1, 0x989680;\n\t"
            "@P1 bra.uni D_%=;\n\t"
            "bra.uni W_%=;\n\t"
            "D_%=:\n\t}"
            :: "r"(a), "r"(parity) : "memory");
    }
}
__device__ __forceinline__ void cluster_sync_() {
    asm volatile("barrier.cluster.arrive.aligned;" ::: "memory");
    asm volatile("barrier.cluster.wait.aligned;" ::: "memory");
}
__device__ __forceinline__ uint32_t ctarank() {
    uint32_t r; asm("mov.u32 %0, %%cluster_ctarank;" : "=r"(r)); return r;
}

// ---- kernel 1: per-chunk-barrier dataflow; 16 warps, half-chunk each ----
__global__ void __launch_bounds__(FWT, 1)
viterbi_fwd(const float* __restrict__ feats, const float* __restrict__ trans,
            float* __restrict__ dout, int idx0)
{
    __shared__ __align__(16) float fvbuf[2][KK];        // buf1 at +2048B
    __shared__ __align__(8) float pval[2][16][NPC];     // parity-double-buffered
    __shared__ __align__(8) unsigned long long cmbar[2][8];  // [parity][chunk]
    __shared__ float tv[FWT];
    __shared__ int   ti[FWT];

    const int tid   = threadIdx.x;
    const int lane  = tid & 31;      // next-row within CTA
    const int w     = tid >> 5;      // warp 0..15
    const int chunk = w & 7;         // prev chunk
    const int half  = w >> 3;        // which 32 of the 64 prevs
    const uint32_t rank = ctarank();
    const int n = (int)rank * NPC + lane;

    // transitions slice trans[n, chunk*64+half*32 .. +32) -> 32 registers
    float Tr[32];
    {
        const float4* tp = (const float4*)(trans + (size_t)n * KK + chunk * 64 + half * 32);
        #pragma unroll
        for (int q = 0; q < 8; q++) {
            float4 v = tp[q];
            Tr[4*q] = v.x; Tr[4*q+1] = v.y; Tr[4*q+2] = v.z; Tr[4*q+3] = v.w;
        }
    }

    const uint32_t mbb = smem_u32(&cmbar[0][0]);   // [par][c] at mbb + par*64 + c*8

    // init fv_{-1} in buf[1]; init barriers; pre-complete [1][c] phase 0
    if (tid < KK) fvbuf[1][tid] = (tid == 0) ? 0.0f : NEGV;
    if (tid < 8) {
        mbar_init(mbb + (uint32_t)tid * 8u, 1);          // [0][tid]
        mbar_init(mbb + 64u + (uint32_t)tid * 8u, 1);    // [1][tid]
        mbar_expect_tx(mbb + 64u + (uint32_t)tid * 8u, CH_TX);
        mbar_complete_tx(mbb + 64u + (uint32_t)tid * 8u, CH_TX);
    }
    __syncthreads();
    cluster_sync_();

    // push: warp w -> dest CTA w; even lanes carry rows (n, n+1);
    // dest chunk barrier index = source rank>>1
    uint32_t rdw, rmw;
    {
        const uint32_t a0 = smem_u32(&fvbuf[0][n]);       // n even for pushing lanes
        const uint32_t mB = mbb + (rank >> 1) * 8u;       // [0][rank>>1]
        rdw = mapa_u32(a0, w);
        rmw = mapa_u32(mB, w);
    }
    const uint32_t myb = mbb + (uint32_t)chunk * 8u;      // my chunk barriers

    // feats prefetch (all lanes, coalesced; redundant across warps -> L1 hit)
    float ft0 = __ldg(feats + n);
    float ft1 = __ldg(feats + KK + n);

    #define STEP(T, PAR) do {                                                      \
        if (w < 8 && lane == 0) mbar_expect_tx(mbb + (PAR)*64u + w*8u, CH_TX);     \
        float ftn;                                                                 \
        {                                                                          \
            int tn = (T) + 2; if (tn > TT - 1) tn = TT - 1;                        \
            ftn = __ldg(feats + (size_t)tn * KK + n);                              \
        }                                                                          \
        mbar_wait(myb + ((PAR)^1)*64u, ((T) >> 1) & 1);   /* my chunk ready */     \
        const float4* fvp = (const float4*)&fvbuf[(PAR) ^ 1][chunk * 64 + half * 32]; \
        float m0 = -INFINITY, m1 = -INFINITY, m2 = -INFINITY, m3 = -INFINITY;      \
        _Pragma("unroll")                                                          \
        for (int q = 0; q < 8; q++) {                                              \
            float4 f = fvp[q];            /* 32-lane broadcast, conflict-free */   \
            m0 = fmaxf(m0, f.x + Tr[4*q]);                                         \
            m1 = fmaxf(m1, f.y + Tr[4*q+1]);                                       \
            m2 = fmaxf(m2, f.z + Tr[4*q+2]);                                       \
            m3 = fmaxf(m3, f.w + Tr[4*q+3]);                                       \
        }                                                                          \
        pval[PAR][w][lane] = fmaxf(fmaxf(m0, m1), fmaxf(m2, m3));                  \
        __syncthreads();                                /* single sync per step */ \
        {                                                                          \
            float v = pval[PAR][0][lane];   /* all warps: identical reduce */      \
            _Pragma("unroll")                                                      \
            for (int c = 1; c < 16; c++) v = fmaxf(v, pval[PAR][c][lane]);         \
            const float fvnew = v + ft0;          /* exact: max + emission */      \
            const float fhi = __shfl_down_sync(0xffffffffu, fvnew, 1);             \
            if ((lane & 1) == 0) {                                                 \
                if (w == 0)                                                        \
                    *(float2*)&g_fv[(size_t)(T) * KK + n] = make_float2(fvnew, fhi);\
                unsigned long long pk =                                            \
                    ((unsigned long long)__float_as_uint(fhi) << 32) |             \
                    (unsigned long long)__float_as_uint(fvnew);                    \
                st_async_b64(rdw + (PAR)*2048u, pk, rmw + (PAR)*64u);              \
            }                                                                      \
        }                                                                          \
        ft0 = ft1; ft1 = ftn;                                                      \
    } while (0)

    for (int t = 0; t < TT; t += 2) {
        STEP(t, 0);
        STEP(t + 1, 1);
    }
    #undef STEP

    // drain final-step messages (buf[1], barrier [1][chunk])
    mbar_wait(myb + 64u, (TT >> 1) & 1);
    __syncthreads();

    // terminal = fv_{TT-1} + trans[1,:]; first-index argmax (rank 0)
    if (rank == 0) {
        const int p = tid;                    // FWT == KK
        const float s = fvbuf[1][p] + trans[KK + p];
        tv[tid] = s; ti[tid] = p;
        __syncthreads();
        if (tid == 0) {
            float bv = tv[0]; int bi = ti[0];
            for (int k = 1; k < FWT; k++)
                if (tv[k] > bv || (tv[k] == bv && ti[k] < bi)) { bv = tv[k]; bi = ti[k]; }
            if (idx0 > 0) dout[0] = bv;
            g_best = bi;
        }
    }
    cluster_sync_();   // keep cluster alive until all remote traffic done
}

// ---- kernel 2: parallel backpointer recompute (exact argmax) ----
__global__ void __launch_bounds__(NTHR, 1)
bp_pass(const float* __restrict__ trans)
{
    __shared__ __align__(16) float fvs[2][KK];   // transposed staging

    const int rblk = blockIdx.x & 15;
    const int g    = blockIdx.x >> 4;
    const int t0   = g * SPAN;
    const int t1   = t0 + SPAN;

    const int tid   = threadIdx.x;
    const int lane  = tid & 31;
    const int w     = tid >> 5;
    const int rl    = lane & 3;
    const int chunk = lane >> 2;
    const int n = rblk * NPC + w * 4 + rl;

    float Tr[64];
    {
        const float4* tp = (const float4*)(trans + (size_t)n * KK + chunk * 64);
        #pragma unroll
        for (int q = 0; q < 16; q++) {
            float4 v = tp[q];
            Tr[4*q] = v.x; Tr[4*q+1] = v.y; Tr[4*q+2] = v.z; Tr[4*q+3] = v.w;
        }
    }

    const int sp = 2 * tid;
    const uint32_t sbyte = (uint32_t)(((sp & 63) >> 2) * 128 + (sp >> 6) * 16 + (sp & 3) * 4);

    float2 pre;
    if (t0 == 0) {
        pre.x = (sp == 0) ? 0.0f : NEGV;
        pre.y = NEGV;
    } else {
        pre = *(const float2*)&g_fv[(size_t)(t0 - 1) * KK + sp];
    }

    int cur = 0;
    for (int t = t0; t < t1; ++t) {
        *(float2*)((char*)&fvs[cur][0] + sbyte) = pre;
        __syncthreads();
        if (t + 1 < t1) pre = *(const float2*)&g_fv[(size_t)t * KK + sp];

        const char* sm = (const char*)&fvs[cur][0] + chunk * 16;
        float bv0 = -INFINITY, bv1 = -INFINITY, bv2 = -INFINITY, bv3 = -INFINITY;
        int   bj0 = 0, bj1 = 0, bj2 = 0, bj3 = 0;
        #pragma unroll
        for (int q = 0; q < 16; q++) {
            float4 f = *(const float4*)(sm + q * 128);
            float s0 = f.x + Tr[4*q],   s1 = f.y + Tr[4*q+1];
            float s2 = f.z + Tr[4*q+2], s3 = f.w + Tr[4*q+3];
            bool g0 = s0 > bv0; bv0 = g0 ? s0 : bv0; bj0 = g0 ? 4*q : bj0;
            bool g1 = s1 > bv1; bv1 = g1 ? s1 : bv1; bj1 = g1 ? 4*q : bj1;
            bool g2 = s2 > bv2; bv2 = g2 ? s2 : bv2; bj2 = g2 ? 4*q : bj2;
            bool g3 = s3 > bv3; bv3 = g3 ? s3 : bv3; bj3 = g3 ? 4*q : bj3;
        }
        int i0 = chunk*64 + bj0, i1 = chunk*64 + bj1 + 1;
        int i2 = chunk*64 + bj2 + 2, i3 = chunk*64 + bj3 + 3;
        if (bv1 > bv0 || (bv1 == bv0 && i1 < i0)) { bv0 = bv1; i0 = i1; }
        if (bv3 > bv2 || (bv3 == bv2 && i3 < i2)) { bv2 = bv3; i2 = i3; }
        if (bv2 > bv0 || (bv2 == bv0 && i2 < i0)) { bv0 = bv2; i0 = i2; }

        float v = bv0; int i = i0;
        #pragma unroll
        for (int d = 4; d <= 16; d <<= 1) {
            float vo = __shfl_xor_sync(0xffffffffu, v, d);
            int   io = __shfl_xor_sync(0xffffffffu, i, d);
            if (vo > v || (vo == v && io < i)) { v = vo; i = io; }
        }
        if (chunk == 0)
            g_bp[(size_t)t * KK + n] = (unsigned short)i;
        cur ^= 1;
    }
}

// ---- kernel 3: per-block backtrack maps ----
__global__ void bt_maps()
{
    __shared__ unsigned short rbuf[KK];
    const int b = blockIdx.x, tid = threadIdx.x;
    int x = tid;
    for (int s = LBT - 1; s >= 0; --s) {
        const size_t t = (size_t)b * LBT + s;
        rbuf[tid] = g_bp[t * KK + tid];
        __syncthreads();
        x = rbuf[x];
        __syncthreads();
    }
    g_maps[b * KK + tid] = (unsigned short)x;
}

// ---- kernel 4: compose block maps ----
__global__ void bt_compose()
{
    int e = g_best;
    g_endtag[BBT - 1] = e;
    for (int b = BBT - 1; b >= 1; --b) {
        e = g_maps[b * KK + e];
        g_endtag[b - 1] = e;
    }
}

// ---- kernel 5: fill best_path ----
__global__ void bt_fill(float* __restrict__ dout, int idx0)
{
    const int b = blockIdx.x;
    int x = g_endtag[b];
    for (int s = LBT - 1; s >= 0; --s) {
        const size_t t = (size_t)b * LBT + s;
        dout[idx0 + t] = (float)x;
        x = g_bp[t * KK + x];
    }
}

extern "C" void kernel_launch(void* const* d_in, const int* in_sizes, int n_in,
                              void* d_out, int out_size)
{
    const float* feats = (const float*)d_in[0];
    const float* trans = (const float*)d_in[1];
    float* out = (float*)d_out;
    int idx0 = out_size - TT; if (idx0 < 0) idx0 = 0;

    cudaFuncSetAttribute(viterbi_fwd,
                         cudaFuncAttributeNonPortableClusterSizeAllowed, 1);
    cudaLaunchConfig_t cfg = {};
    cfg.gridDim  = dim3(CSZ, 1, 1);
    cfg.blockDim = dim3(FWT, 1, 1);
    cfg.dynamicSmemBytes = 0;
    cfg.stream = 0;
    cudaLaunchAttribute at[1];
    at[0].id = cudaLaunchAttributeClusterDimension;
    at[0].val.clusterDim.x = CSZ;
    at[0].val.clusterDim.y = 1;
    at[0].val.clusterDim.z = 1;
    cfg.attrs = at; cfg.numAttrs = 1;
    cudaLaunchKernelEx(&cfg, viterbi_fwd, feats, trans, out, idx0);

    bp_pass<<<16 * GG, NTHR>>>(trans);
    bt_maps<<<BBT, KK>>>();
    bt_compose<<<1, 1>>>();
    bt_fill<<<BBT, 1>>>(out, idx0);
}

// round 17
// speedup vs baseline: 1.6209x; 1.3858x over previous
#include <cuda_runtime.h>
#include <cstdint>

#define TT 65536
#define KK 512
#define NEGV (-10000.0f)
#define CSZ 16
#define NPC 32
#define NTHR 256
#define LBT 256
#define BBT (TT/LBT)
#define CH_TX 256u
#define GG 64
#define SPAN (TT/GG)
#define FWD_CTAS 16
#define BP_CTAS (16*GG)
#define GRID_CTAS (FWD_CTAS + BP_CTAS + BBT)   // 16+1024+256 = 1296

// ---- static device scratch ----
__device__ float          g_fv[(size_t)TT * KK];
__device__ unsigned short g_bp[(size_t)TT * KK];
__device__ unsigned short g_maps[BBT * KK];
__device__ int            g_endtag[BBT];
__device__ int            g_best;
__device__ int            g_prog[16];     // forward progress per rank (rows < v valid)
__device__ int            g_bpdone[GG];   // finished bp CTAs per partition

__device__ __forceinline__ uint32_t smem_u32(const void* p) {
    return (uint32_t)__cvta_generic_to_shared(p);
}
__device__ __forceinline__ uint32_t mapa_u32(uint32_t laddr, int r) {
    uint32_t ra;
    asm("mapa.shared::cluster.u32 %0, %1, %2;" : "=r"(ra) : "r"(laddr), "r"(r));
    return ra;
}
__device__ __forceinline__ void st_async_b64(uint32_t raddr, unsigned long long v,
                                             uint32_t rmbar) {
    asm volatile(
        "st.async.weak.shared::cluster.mbarrier::complete_tx::bytes.b64 [%0], %1, [%2];"
        :: "r"(raddr), "l"(v), "r"(rmbar) : "memory");
}
__device__ __forceinline__ void mbar_init(uint32_t a, uint32_t cnt) {
    asm volatile("mbarrier.init.shared.b64 [%0], %1;" :: "r"(a), "r"(cnt) : "memory");
}
__device__ __forceinline__ void mbar_expect_tx(uint32_t a, uint32_t bytes) {
    asm volatile("mbarrier.arrive.expect_tx.shared.b64 _, [%0], %1;"
                 :: "r"(a), "r"(bytes) : "memory");
}
__device__ __forceinline__ void mbar_complete_tx(uint32_t a, uint32_t bytes) {
    asm volatile("mbarrier.complete_tx.shared.b64 [%0], %1;"
                 :: "r"(a), "r"(bytes) : "memory");
}
__device__ __forceinline__ void mbar_wait(uint32_t a, uint32_t parity) {
    uint32_t done;
    asm volatile(
        "{\n\t.reg .pred p;\n\t"
        "mbarrier.try_wait.parity.acquire.cta.shared::cta.b64 p, [%1], %2;\n\t"
        "selp.b32 %0, 1, 0, p;\n\t}"
        : "=r"(done) : "r"(a), "r"(parity) : "memory");
    if (!done) {
        asm volatile(
            "{\n\t.reg .pred P1;\n\t"
            "W_%=:\n\t"
            "mbarrier.try_wait.parity.acquire.cta.shared::cta.b64 P1, [%0], %1, 0x989680;\n\t"
            "@P1 bra.uni D_%=;\n\t"
            "bra.uni W_%=;\n\t"
            "D_%=:\n\t}"
            :: "r"(a), "r"(parity) : "memory");
    }
}
__device__ __forceinline__ void cluster_sync_() {
    asm volatile("barrier.cluster.arrive.aligned;" ::: "memory");
    asm volatile("barrier.cluster.wait.aligned;" ::: "memory");
}
__device__ __forceinline__ uint32_t ctarank() {
    uint32_t r; asm("mov.u32 %0, %%cluster_ctarank;" : "=r"(r)); return r;
}

struct FwdShm {
    float fvbuf[2][KK];                 // buf1 at +2048B
    float pval[2][8][NPC];
    unsigned long long cmbar[2][8];
    float tv[NTHR];
    int   ti[NTHR];
};
struct BpShm { float fvs[2][KK]; };

// ---- mega kernel: forward (cluster 0) + bp_pass + bt_maps, overlapped ----
__global__ void __launch_bounds__(NTHR, 1)
mega(const float* __restrict__ feats, const float* __restrict__ trans,
     float* __restrict__ dout, int idx0)
{
    __shared__ __align__(16) unsigned char shm[sizeof(FwdShm)];
    const int bx  = blockIdx.x;
    const int tid = threadIdx.x;

    if (bx < FWD_CTAS) {
        // ================= forward pass (R12 verbatim, tiled loop) ==========
        FwdShm* S = (FwdShm*)shm;
        const int lane = tid & 31;
        const int w    = tid >> 5;
        const uint32_t rank = ctarank();
        const int n = (int)rank * NPC + lane;

        float Tr[64];
        {
            const float4* tp = (const float4*)(trans + (size_t)n * KK + w * 64);
            #pragma unroll
            for (int q = 0; q < 16; q++) {
                float4 v = tp[q];
                Tr[4*q] = v.x; Tr[4*q+1] = v.y; Tr[4*q+2] = v.z; Tr[4*q+3] = v.w;
            }
        }

        const uint32_t mbb = smem_u32(&S->cmbar[0][0]);

        for (int p = tid; p < KK; p += NTHR) S->fvbuf[1][p] = (p == 0) ? 0.0f : NEGV;
        if (tid < 8) {
            mbar_init(mbb + (uint32_t)tid * 8u, 1);
            mbar_init(mbb + 64u + (uint32_t)tid * 8u, 1);
            mbar_expect_tx(mbb + 64u + (uint32_t)tid * 8u, CH_TX);
            mbar_complete_tx(mbb + 64u + (uint32_t)tid * 8u, CH_TX);
        }
        __syncthreads();
        cluster_sync_();

        uint32_t rd0, rd1, rm0, rm1;
        {
            const uint32_t a0 = smem_u32(&S->fvbuf[0][n]);
            const uint32_t mB = mbb + (rank >> 1) * 8u;
            rd0 = mapa_u32(a0, 2 * w);
            rd1 = mapa_u32(a0, 2 * w + 1);
            rm0 = mapa_u32(mB, 2 * w);
            rm1 = mapa_u32(mB, 2 * w + 1);
        }
        const uint32_t myb = mbb + (uint32_t)w * 8u;

        float ft0 = __ldg(feats + n);
        float ft1 = __ldg(feats + KK + n);

        #define STEP(T, PAR) do {                                                  \
            if (tid == 0) mbar_expect_tx((PAR) ? myb + 64u - (uint32_t)w*8u + (uint32_t)w*8u : myb, 0), (void)0; \
        } while (0)
        #undef STEP
        // (macro above unused; real STEP below — kept minimal to avoid typos)
        #define STEP2(T, PAR) do {                                                 \
            if (lane == 0) mbar_expect_tx(mbb + (PAR)*64u + (uint32_t)w*8u, CH_TX);\
            float ftn;                                                             \
            {                                                                      \
                int tn = (T) + 2; if (tn > TT - 1) tn = TT - 1;                    \
                ftn = __ldg(feats + (size_t)tn * KK + n);                          \
            }                                                                      \
            mbar_wait(myb + ((PAR)^1)*64u, ((T) >> 1) & 1);                        \
            const float4* fvp = (const float4*)&S->fvbuf[(PAR) ^ 1][w * 64];       \
            float m0 = -INFINITY, m1 = -INFINITY, m2 = -INFINITY, m3 = -INFINITY;  \
            _Pragma("unroll")                                                      \
            for (int q = 0; q < 16; q++) {                                         \
                float4 f = fvp[q];                                                 \
                m0 = fmaxf(m0, f.x + Tr[4*q]);                                     \
                m1 = fmaxf(m1, f.y + Tr[4*q+1]);                                   \
                m2 = fmaxf(m2, f.z + Tr[4*q+2]);                                   \
                m3 = fmaxf(m3, f.w + Tr[4*q+3]);                                   \
            }                                                                      \
            S->pval[PAR][w][lane] = fmaxf(fmaxf(m0, m1), fmaxf(m2, m3));           \
            __syncthreads();                                                       \
            {                                                                      \
                float v = S->pval[PAR][0][lane];                                   \
                _Pragma("unroll")                                                  \
                for (int c = 1; c < 8; c++) v = fmaxf(v, S->pval[PAR][c][lane]);   \
                const float fvnew = v + ft0;                                       \
                const float fhi = __shfl_down_sync(0xffffffffu, fvnew, 1);         \
                if ((lane & 1) == 0) {                                             \
                    if (w == 0)                                                    \
                        *(float2*)&g_fv[(size_t)(T) * KK + n] = make_float2(fvnew, fhi);\
                    unsigned long long pk =                                        \
                        ((unsigned long long)__float_as_uint(fhi) << 32) |         \
                        (unsigned long long)__float_as_uint(fvnew);                \
                    st_async_b64(rd0 + (PAR)*2048u, pk, rm0 + (PAR)*64u);          \
                    st_async_b64(rd1 + (PAR)*2048u, pk, rm1 + (PAR)*64u);          \
                }                                                                  \
            }                                                                      \
            ft0 = ft1; ft1 = ftn;                                                  \
        } while (0)

        for (int tb = 0; tb < TT; tb += 2048) {
            for (int t = tb; t < tb + 2048; t += 2) {
                STEP2(t, 0);
                STEP2(t + 1, 1);
            }
            if (tid == 0) {          // publish progress: rows < tb+2047 valid
                __threadfence();
                *(volatile int*)&g_prog[rank] = tb + 2047;
            }
        }
        #undef STEP2

        mbar_wait(myb + 64u, (TT >> 1) & 1);
        __syncthreads();
        if (tid == 0) { __threadfence(); *(volatile int*)&g_prog[rank] = TT + 1; }

        if (rank == 0) {
            float v = -INFINITY; int i = 0;
            #pragma unroll
            for (int k = 0; k < KK / NTHR; k++) {
                const int p = tid * (KK / NTHR) + k;
                const float s = S->fvbuf[1][p] + trans[KK + p];
                if (s > v) { v = s; i = p; }
            }
            S->tv[tid] = v; S->ti[tid] = i;
            __syncthreads();
            if (tid == 0) {
                float bv = S->tv[0]; int bi = S->ti[0];
                for (int k = 1; k < NTHR; k++)
                    if (S->tv[k] > bv || (S->tv[k] == bv && S->ti[k] < bi)) { bv = S->tv[k]; bi = S->ti[k]; }
                if (idx0 > 0) dout[0] = bv;
                g_best = bi;
            }
        }
        cluster_sync_();
        return;
    }

    if (bx < FWD_CTAS + BP_CTAS) {
        // ================= bp_pass (gated on forward progress) ==============
        BpShm* S = (BpShm*)shm;
        const int b    = bx - FWD_CTAS;
        const int rblk = b & 15;
        const int g    = b >> 4;
        const int t0   = g * SPAN;
        const int t1   = t0 + SPAN;

        const int lane  = tid & 31;
        const int w     = tid >> 5;
        const int rl    = lane & 3;
        const int chunk = lane >> 2;
        const int n = rblk * NPC + w * 4 + rl;

        float Tr[64];
        {
            const float4* tp = (const float4*)(trans + (size_t)n * KK + chunk * 64);
            #pragma unroll
            for (int q = 0; q < 16; q++) {
                float4 v = tp[q];
                Tr[4*q] = v.x; Tr[4*q+1] = v.y; Tr[4*q+2] = v.z; Tr[4*q+3] = v.w;
            }
        }

        // gate: need g_fv rows <= t1-2  ->  min prog >= t1-1
        if (tid == 0) {
            for (;;) {
                int m = 0x7fffffff;
                #pragma unroll
                for (int r = 0; r < 16; r++) {
                    int v = *(volatile int*)&g_prog[r];
                    m = (v < m) ? v : m;
                }
                if (m >= t1 - 1) break;
                __nanosleep(2000);
            }
            __threadfence();
        }
        __syncthreads();

        const int sp = 2 * tid;
        const uint32_t sbyte = (uint32_t)(((sp & 63) >> 2) * 128 + (sp >> 6) * 16 + (sp & 3) * 4);

        float2 pre;
        if (t0 == 0) {
            pre.x = (sp == 0) ? 0.0f : NEGV;
            pre.y = NEGV;
        } else {
            pre = *(const float2*)&g_fv[(size_t)(t0 - 1) * KK + sp];
        }

        int cur = 0;
        for (int t = t0; t < t1; ++t) {
            *(float2*)((char*)&S->fvs[cur][0] + sbyte) = pre;
            __syncthreads();
            if (t + 1 < t1) pre = *(const float2*)&g_fv[(size_t)t * KK + sp];

            const char* sm = (const char*)&S->fvs[cur][0] + chunk * 16;
            float bv0 = -INFINITY, bv1 = -INFINITY, bv2 = -INFINITY, bv3 = -INFINITY;
            int   bj0 = 0, bj1 = 0, bj2 = 0, bj3 = 0;
            #pragma unroll
            for (int q = 0; q < 16; q++) {
                float4 f = *(const float4*)(sm + q * 128);
                float s0 = f.x + Tr[4*q],   s1 = f.y + Tr[4*q+1];
                float s2 = f.z + Tr[4*q+2], s3 = f.w + Tr[4*q+3];
                bool g0 = s0 > bv0; bv0 = g0 ? s0 : bv0; bj0 = g0 ? 4*q : bj0;
                bool g1 = s1 > bv1; bv1 = g1 ? s1 : bv1; bj1 = g1 ? 4*q : bj1;
                bool g2 = s2 > bv2; bv2 = g2 ? s2 : bv2; bj2 = g2 ? 4*q : bj2;
                bool g3 = s3 > bv3; bv3 = g3 ? s3 : bv3; bj3 = g3 ? 4*q : bj3;
            }
            int i0 = chunk*64 + bj0, i1 = chunk*64 + bj1 + 1;
            int i2 = chunk*64 + bj2 + 2, i3 = chunk*64 + bj3 + 3;
            if (bv1 > bv0 || (bv1 == bv0 && i1 < i0)) { bv0 = bv1; i0 = i1; }
            if (bv3 > bv2 || (bv3 == bv2 && i3 < i2)) { bv2 = bv3; i2 = i3; }
            if (bv2 > bv0 || (bv2 == bv0 && i2 < i0)) { bv0 = bv2; i0 = i2; }

            float v = bv0; int i = i0;
            #pragma unroll
            for (int d = 4; d <= 16; d <<= 1) {
                float vo = __shfl_xor_sync(0xffffffffu, v, d);
                int   io = __shfl_xor_sync(0xffffffffu, i, d);
                if (vo > v || (vo == v && io < i)) { v = vo; i = io; }
            }
            if (chunk == 0)
                g_bp[(size_t)t * KK + n] = (unsigned short)i;
            cur ^= 1;
        }
        __syncthreads();
        if (tid == 0) { __threadfence(); atomicAdd(&g_bpdone[g], 1); }
        return;
    }

    // ================= bt_maps (gated on bp partition completion) ===========
    {
        unsigned short* rbuf = (unsigned short*)shm;   // 512 u16 = 1KB
        const int b = bx - FWD_CTAS - BP_CTAS;

        if (tid == 0) {
            while (atomicAdd(&g_bpdone[b >> 2], 0) < 16) __nanosleep(2000);
            __threadfence();
        }
        __syncthreads();

        int x1 = tid, x2 = tid + 256;
        for (int s = LBT - 1; s >= 0; --s) {
            const size_t t = (size_t)b * LBT + s;
            rbuf[tid]       = g_bp[t * KK + tid];
            rbuf[tid + 256] = g_bp[t * KK + tid + 256];
            __syncthreads();
            x1 = rbuf[x1]; x2 = rbuf[x2];
            __syncthreads();
        }
        g_maps[b * KK + tid]       = (unsigned short)x1;
        g_maps[b * KK + tid + 256] = (unsigned short)x2;
    }
}

// ---- kernel 2: compose block maps ----
__global__ void bt_compose()
{
    int e = g_best;
    g_endtag[BBT - 1] = e;
    for (int b = BBT - 1; b >= 1; --b) {
        e = g_maps[b * KK + e];
        g_endtag[b - 1] = e;
    }
}

// ---- kernel 3: fill best_path (+ reset gates for next replay) ----
__global__ void bt_fill(float* __restrict__ dout, int idx0)
{
    const int b = blockIdx.x;
    int x = g_endtag[b];
    for (int s = LBT - 1; s >= 0; --s) {
        const size_t t = (size_t)b * LBT + s;
        dout[idx0 + t] = (float)x;
        x = g_bp[t * KK + x];
    }
    if (b == 0) {
        for (int i = 0; i < 16; i++) g_prog[i] = 0;
        for (int i = 0; i < GG; i++) g_bpdone[i] = 0;
    }
}

extern "C" void kernel_launch(void* const* d_in, const int* in_sizes, int n_in,
                              void* d_out, int out_size)
{
    const float* feats = (const float*)d_in[0];
    const float* trans = (const float*)d_in[1];
    float* out = (float*)d_out;
    int idx0 = out_size - TT; if (idx0 < 0) idx0 = 0;

    cudaFuncSetAttribute(mega, cudaFuncAttributeNonPortableClusterSizeAllowed, 1);
    cudaLaunchConfig_t cfg = {};
    cfg.gridDim  = dim3(GRID_CTAS, 1, 1);
    cfg.blockDim = dim3(NTHR, 1, 1);
    cfg.dynamicSmemBytes = 0;
    cfg.stream = 0;
    cudaLaunchAttribute at[1];
    at[0].id = cudaLaunchAttributeClusterDimension;
    at[0].val.clusterDim.x = CSZ;
    at[0].val.clusterDim.y = 1;
    at[0].val.clusterDim.z = 1;
    cfg.attrs = at; cfg.numAttrs = 1;
    cudaLaunchKernelEx(&cfg, mega, feats, trans, out, idx0);

    bt_compose<<<1, 1>>>();
    bt_fill<<<BBT, 1>>>(out, idx0);
}